// round 1
// baseline (speedup 1.0000x reference)
#include <cuda_runtime.h>
#include <cstdint>

#define Hdim 128
#define KSUB 16
#define SK_C 128000
#define N_C  60000
#define S_C  8000
#define L_C  3
#define HH   (Hdim * Hdim)

#define FLAG_RELU  1
#define FLAG_ACCUM 2

#define CDIV(a, b) (((a) + (b) - 1) / (b))

// ------------------------- scratch (static device globals) -------------------------
__device__ float g_h[SK_C * Hdim];
__device__ float g_acc[SK_C * Hdim];
__device__ float g_agg[SK_C * Hdim];
__device__ float g_tmp[SK_C * Hdim];
__device__ float g_xsum[N_C * Hdim];
__device__ float g_aggN[N_C * Hdim];   // reused as yvv output
__device__ float g_h2[N_C * Hdim];
__device__ float g_xvvc[N_C * Hdim];
__device__ float g_ykk[S_C * Hdim];
__device__ int   g_cnt[N_C];
__device__ int   g_rcnt[N_C];
__device__ float g_wt[L_C * 7 * HH];

// ------------------------- f32x2 helpers -------------------------
__device__ __forceinline__ unsigned long long pk2(float x, float y) {
    unsigned long long r;
    asm("mov.b64 %0, {%1, %2};" : "=l"(r) : "f"(x), "f"(y));
    return r;
}
__device__ __forceinline__ void ffma2(unsigned long long& d, unsigned long long a, unsigned long long b) {
    asm("fma.rn.f32x2 %0, %1, %2, %0;" : "+l"(d) : "l"(a), "l"(b));
}

// ------------------------- weight transpose: WT[k][o] = W[o][k] -------------------------
__global__ void transpose_all(const float* __restrict__ s0, const float* __restrict__ s1,
                              const float* __restrict__ s2, const float* __restrict__ s3,
                              const float* __restrict__ s4, const float* __restrict__ s5,
                              const float* __restrict__ s6, float* __restrict__ dst, int L)
{
    int i = blockIdx.x * blockDim.x + threadIdx.x;
    int total = L * 7 * HH;
    if (i >= total) return;
    int m = i >> 14;          // matrix index (l*7+j)
    int r = i & (HH - 1);
    int k = r >> 7, o = r & 127;
    int l = m / 7, j = m % 7;
    const float* base;
    switch (j) {
        case 0: base = s0; break;
        case 1: base = s1; break;
        case 2: base = s2; break;
        case 3: base = s3; break;
        case 4: base = s4; break;
        case 5: base = s5; break;
        default: base = s6; break;
    }
    dst[i] = base[(size_t)l * HH + o * Hdim + k];
}

// ------------------------- SGEMM: Y[M,128] = ep((X1 [+X2]) @ WT + bias) -------------------------
// WT is k-major: WT[k*128 + o].  Tile 128x128, 256 threads, 8x8 per thread (f32x2 over col pairs).
__global__ __launch_bounds__(256, 2)
void gemm128(const float* __restrict__ X1, const float* __restrict__ X2,
             const float* __restrict__ WT, const float* __restrict__ bias,
             const float* __restrict__ gamma, const float* __restrict__ beta,
             float* __restrict__ Y, int M, long inStride, int flags)
{
    __shared__ float Ws[32 * Hdim];     // [k][o]
    __shared__ float Xs[128 * 34];      // [r][kk], stride 34 (bank-conflict-free a-loads)

    const int tid = threadIdx.x;
    const int m0 = blockIdx.x * 128;
    const int cg = tid & 15;            // column group
    const int rg = tid >> 4;            // row group (rows rg*8 .. rg*8+7)

    unsigned long long acc[8][4];
#pragma unroll
    for (int r = 0; r < 8; r++)
#pragma unroll
        for (int t = 0; t < 4; t++) acc[r][t] = 0ULL;

#pragma unroll 1
    for (int k0 = 0; k0 < Hdim; k0 += 32) {
        // load W chunk (32x128 floats, fully coalesced)
        {
            const float4* wsrc = (const float4*)(WT + k0 * Hdim);
            float4* wdst = (float4*)Ws;
#pragma unroll
            for (int i = 0; i < 4; i++)
                wdst[tid + i * 256] = wsrc[tid + i * 256];
        }
        // load X chunk (128 rows x 32 cols)
#pragma unroll
        for (int i = 0; i < 4; i++) {
            int idx = tid + i * 256;     // 0..1023
            int r = idx >> 3;
            int c4 = idx & 7;
            float4 v = make_float4(0.f, 0.f, 0.f, 0.f);
            int m = m0 + r;
            if (m < M) {
                v = *(const float4*)(X1 + (long)m * inStride + k0 + c4 * 4);
                if (X2) {
                    float4 u = *(const float4*)(X2 + (long)m * Hdim + k0 + c4 * 4);
                    v.x += u.x; v.y += u.y; v.z += u.z; v.w += u.w;
                }
            }
            float* xd = &Xs[r * 34 + c4 * 4];
            *(float2*)(xd)     = make_float2(v.x, v.y);
            *(float2*)(xd + 2) = make_float2(v.z, v.w);
        }
        __syncthreads();

#pragma unroll 4
        for (int kk = 0; kk < 32; kk += 2) {
            float2 a2[8];
#pragma unroll
            for (int r = 0; r < 8; r++)
                a2[r] = *(const float2*)&Xs[(rg * 8 + r) * 34 + kk];
            unsigned long long b0[4], b1[4];
#pragma unroll
            for (int t = 0; t < 4; t++) {
                b0[t] = *(const unsigned long long*)&Ws[kk * Hdim + t * 32 + cg * 2];
                b1[t] = *(const unsigned long long*)&Ws[(kk + 1) * Hdim + t * 32 + cg * 2];
            }
#pragma unroll
            for (int r = 0; r < 8; r++) {
                unsigned long long ax = pk2(a2[r].x, a2[r].x);
                unsigned long long ay = pk2(a2[r].y, a2[r].y);
#pragma unroll
                for (int t = 0; t < 4; t++) {
                    ffma2(acc[r][t], ax, b0[t]);
                    ffma2(acc[r][t], ay, b1[t]);
                }
            }
        }
        __syncthreads();
    }

    // epilogue
    float2 bia[4], gam[4], bet[4];
#pragma unroll
    for (int t = 0; t < 4; t++) {
        int o = t * 32 + cg * 2;
        bia[t] = *(const float2*)&bias[o];
        if (gamma) { gam[t] = *(const float2*)&gamma[o]; bet[t] = *(const float2*)&beta[o]; }
    }
#pragma unroll
    for (int r = 0; r < 8; r++) {
        int m = m0 + rg * 8 + r;
        if (m < M) {
#pragma unroll
            for (int t = 0; t < 4; t++) {
                int o = t * 32 + cg * 2;
                float x = __uint_as_float((unsigned)(acc[r][t]));
                float y = __uint_as_float((unsigned)(acc[r][t] >> 32));
                x += bia[t].x; y += bia[t].y;
                if (gamma) { x = x * gam[t].x + bet[t].x; y = y * gam[t].y + bet[t].y; }
                if (flags & FLAG_RELU) { x = fmaxf(x, 0.f); y = fmaxf(y, 0.f); }
                float2* yp = (float2*)&Y[(long)m * Hdim + o];
                if (flags & FLAG_ACCUM) { float2 old = *yp; x += old.x; y += old.y; }
                *yp = make_float2(x, y);
            }
        }
    }
}

// ------------------------- edge message passing: agg[dst] += relu(x[src] + bond[bid]) -------------------------
__global__ void edge_msg(const float* __restrict__ xin, const int* __restrict__ src,
                         const int* __restrict__ dst, const int* __restrict__ bid,
                         const float* __restrict__ bond, float* __restrict__ agg, int E)
{
    int w = (blockIdx.x * blockDim.x + threadIdx.x) >> 5;
    int l = threadIdx.x & 31;
    if (w >= E) return;
    int s = __ldg(src + w), d = __ldg(dst + w), b = __ldg(bid + w);
    float4 hv = *(const float4*)(xin + (size_t)s * Hdim + l * 4);
    float4 bv = *(const float4*)(bond + (size_t)b * Hdim + l * 4);
    float m0 = fmaxf(hv.x + bv.x, 0.f);
    float m1 = fmaxf(hv.y + bv.y, 0.f);
    float m2 = fmaxf(hv.z + bv.z, 0.f);
    float m3 = fmaxf(hv.w + bv.w, 0.f);
    float* o = agg + (size_t)d * Hdim + l * 4;
    atomicAdd(o + 0, m0);
    atomicAdd(o + 1, m1);
    atomicAdd(o + 2, m2);
    atomicAdd(o + 3, m3);
}

// ------------------------- counts -------------------------
__global__ void count_kernel(const int* __restrict__ node_ids, int* __restrict__ cnt, int SKn)
{
    int i = blockIdx.x * blockDim.x + threadIdx.x;
    if (i >= SKn) return;
    int nid = node_ids[i];
    if (nid >= 0) atomicAdd(&cnt[nid], 1);
}
__global__ void rcount_kernel(const int* __restrict__ node_ids, int* __restrict__ rcnt, int Sn)
{
    int s = blockIdx.x * blockDim.x + threadIdx.x;
    if (s >= Sn) return;
    int nid = node_ids[s * KSUB];
    if (nid >= 0) atomicAdd(&rcnt[nid], 1);
}

// ------------------------- init h -------------------------
__global__ void init_h(const float* __restrict__ atom_table, const float* __restrict__ role_table,
                       const int* __restrict__ atom_ids, const int* __restrict__ node_ids,
                       float* __restrict__ h, int SKn)
{
    int t = blockIdx.x * blockDim.x + threadIdx.x;
    int row = t >> 5;
    if (row >= SKn) return;
    int q = t & 31;
    float4 out = make_float4(0.f, 0.f, 0.f, 0.f);
    if (node_ids[row] >= 0) {
        int aid = atom_ids[row];
        float4 v = *(const float4*)(atom_table + (size_t)aid * Hdim + q * 4);
        const float* role = role_table + (((row & (KSUB - 1)) == 0) ? Hdim : 0);
        float4 r = *(const float4*)(role + q * 4);
        out = make_float4(v.x + r.x, v.y + r.y, v.z + r.z, v.w + r.w);
    }
    *(float4*)(h + (size_t)row * Hdim + q * 4) = out;
}

// ------------------------- scatter add: dst[nid] += src[row] -------------------------
__global__ void scatter_add(const float* __restrict__ src, const int* __restrict__ node_ids,
                            float* __restrict__ dst, int SKn)
{
    int t = blockIdx.x * blockDim.x + threadIdx.x;
    int row = t >> 5;
    if (row >= SKn) return;
    int nid = node_ids[row];
    if (nid < 0) return;
    int q = t & 31;
    float4 v = *(const float4*)(src + (size_t)row * Hdim + q * 4);
    float* o = dst + (size_t)nid * Hdim + q * 4;
    atomicAdd(o + 0, v.x);
    atomicAdd(o + 1, v.y);
    atomicAdd(o + 2, v.z);
    atomicAdd(o + 3, v.w);
}

__global__ void root_scatter(const float* __restrict__ h, const int* __restrict__ node_ids,
                             float* __restrict__ dst, int Sn)
{
    int t = blockIdx.x * blockDim.x + threadIdx.x;
    int s = t >> 5;
    if (s >= Sn) return;
    int row = s * KSUB;
    int nid = node_ids[row];
    if (nid < 0) return;
    int q = t & 31;
    float4 v = *(const float4*)(h + (size_t)row * Hdim + q * 4);
    float* o = dst + (size_t)nid * Hdim + q * 4;
    atomicAdd(o + 0, v.x);
    atomicAdd(o + 1, v.y);
    atomicAdd(o + 2, v.z);
    atomicAdd(o + 3, v.w);
}

// ------------------------- scale rows by 1/max(cnt,1) -------------------------
__global__ void scale_rows(float* __restrict__ x, const int* __restrict__ cnt, int Nn)
{
    int t = blockIdx.x * blockDim.x + threadIdx.x;
    int n = t >> 5;
    if (n >= Nn) return;
    int q = t & 31;
    float inv = 1.f / (float)max(cnt[n], 1);
    float4* p = (float4*)(x + (size_t)n * Hdim + q * 4);
    float4 v = *p;
    v.x *= inv; v.y *= inv; v.z *= inv; v.w *= inv;
    *p = v;
}

// ------------------------- per-layer combine -------------------------
__global__ void combine_kernel(const float* __restrict__ acc, const float* __restrict__ h2,
                               const float* __restrict__ yvv, const float* __restrict__ ykk,
                               const int* __restrict__ node_ids, const int* __restrict__ sub_batch,
                               float* __restrict__ h, int SKn)
{
    int t = blockIdx.x * blockDim.x + threadIdx.x;
    int row = t >> 5;
    if (row >= SKn) return;
    int q = t & 31;
    int nid = node_ids[row];
    float4 out = make_float4(0.f, 0.f, 0.f, 0.f);
    if (nid >= 0) {
        int sb = sub_batch[row];
        float4 a = *(const float4*)(acc + (size_t)row * Hdim + q * 4);
        float4 b = *(const float4*)(h2  + (size_t)nid * Hdim + q * 4);
        float4 c = *(const float4*)(yvv + (size_t)nid * Hdim + q * 4);
        float4 d = *(const float4*)(ykk + (size_t)sb  * Hdim + q * 4);
        out.x = fmaxf(a.x + b.x + c.x + d.x, 0.f);
        out.y = fmaxf(a.y + b.y + c.y + d.y, 0.f);
        out.z = fmaxf(a.z + b.z + c.z + d.z, 0.f);
        out.w = fmaxf(a.w + b.w + c.w + d.w, 0.f);
    }
    *(float4*)(h + (size_t)row * Hdim + q * 4) = out;
}

// ------------------------- final pool: out[batch[n]] += xsum[n] / max(cnt[n],1) -------------------------
__global__ void pool_kernel(const float* __restrict__ xsum, const int* __restrict__ cnt,
                            const int* __restrict__ batch, float* __restrict__ out, int Nn)
{
    int t = blockIdx.x * blockDim.x + threadIdx.x;
    int n = t >> 5;
    if (n >= Nn) return;
    int q = t & 31;
    float inv = 1.f / (float)max(cnt[n], 1);
    int g = batch[n];
    float4 v = *(const float4*)(xsum + (size_t)n * Hdim + q * 4);
    float* o = out + (size_t)g * Hdim + q * 4;
    atomicAdd(o + 0, v.x * inv);
    atomicAdd(o + 1, v.y * inv);
    atomicAdd(o + 2, v.z * inv);
    atomicAdd(o + 3, v.w * inv);
}

// ------------------------- host orchestration -------------------------
extern "C" void kernel_launch(void* const* d_in, const int* in_sizes, int n_in,
                              void* d_out, int out_size)
{
    const float* atom_table = (const float*)d_in[0];
    const float* bond_table = (const float*)d_in[1];
    const float* role_table = (const float*)d_in[2];
    const float* lW1  = (const float*)d_in[3];
    const float* lb1  = (const float*)d_in[4];
    const float* lW2  = (const float*)d_in[5];
    const float* lb2  = (const float*)d_in[6];
    const float* gW1  = (const float*)d_in[7];
    const float* gb1  = (const float*)d_in[8];
    const float* gW2  = (const float*)d_in[9];
    const float* gb2  = (const float*)d_in[10];
    const float* lbn_g = (const float*)d_in[11];
    const float* lbn_b = (const float*)d_in[12];
    const float* gbn_g = (const float*)d_in[13];
    const float* gbn_b = (const float*)d_in[14];
    const float* skipW = (const float*)d_in[15];
    const float* skipb = (const float*)d_in[16];
    const float* vvW  = (const float*)d_in[17];
    const float* vvb  = (const float*)d_in[18];
    const float* kkW  = (const float*)d_in[19];
    const float* kkb  = (const float*)d_in[20];
    const int* atom_ids  = (const int*)d_in[21];
    const int* bid_i     = (const int*)d_in[22];
    const int* bid_g     = (const int*)d_in[23];
    const int* intra_ei  = (const int*)d_in[24];
    const int* node_ids  = (const int*)d_in[25];
    const int* edge_index = (const int*)d_in[26];
    const int* sub_batch = (const int*)d_in[27];
    const int* batch     = (const int*)d_in[28];

    const int SKn = in_sizes[21];
    const int EIn = in_sizes[22];
    const int EGn = in_sizes[23];
    const int Nn  = in_sizes[28];
    const int Sn  = SKn / KSUB;
    const int L   = in_sizes[4] / Hdim;

    float *h, *acc, *agg, *tmp, *xsum, *aggN, *h2, *xvvc, *ykk, *wt;
    int *cnt, *rcnt;
    cudaGetSymbolAddress((void**)&h,    g_h);
    cudaGetSymbolAddress((void**)&acc,  g_acc);
    cudaGetSymbolAddress((void**)&agg,  g_agg);
    cudaGetSymbolAddress((void**)&tmp,  g_tmp);
    cudaGetSymbolAddress((void**)&xsum, g_xsum);
    cudaGetSymbolAddress((void**)&aggN, g_aggN);
    cudaGetSymbolAddress((void**)&h2,   g_h2);
    cudaGetSymbolAddress((void**)&xvvc, g_xvvc);
    cudaGetSymbolAddress((void**)&ykk,  g_ykk);
    cudaGetSymbolAddress((void**)&wt,   g_wt);
    cudaGetSymbolAddress((void**)&cnt,  g_cnt);
    cudaGetSymbolAddress((void**)&rcnt, g_rcnt);

    const int TB = 256;
    const size_t skBytes = (size_t)SKn * Hdim * sizeof(float);
    const size_t nBytes  = (size_t)Nn  * Hdim * sizeof(float);

    // one-time per call: weight transposes + counts + init
    transpose_all<<<CDIV(L * 7 * HH, TB), TB>>>(skipW, lW1, lW2, gW1, gW2, vvW, kkW, wt, L);
    cudaMemsetAsync(cnt,  0, (size_t)Nn * sizeof(int));
    cudaMemsetAsync(rcnt, 0, (size_t)Nn * sizeof(int));
    count_kernel<<<CDIV(SKn, TB), TB>>>(node_ids, cnt, SKn);
    rcount_kernel<<<CDIV(Sn, TB), TB>>>(node_ids, rcnt, Sn);
    init_h<<<CDIV(SKn * 32, TB), TB>>>(atom_table, role_table, atom_ids, node_ids, h, SKn);

    for (int l = 0; l < L; l++) {
        const float* wt_l = wt + (size_t)l * 7 * HH;

        // local GINE aggregation
        cudaMemsetAsync(agg, 0, skBytes);
        edge_msg<<<CDIV(EIn * 32, TB), TB>>>(h, intra_ei, intra_ei + EIn, bid_i, bond_table, agg, EIn);

        // skip path -> acc
        gemm128<<<CDIV(SKn, 128), TB>>>(h, nullptr, wt_l + 0 * HH, skipb + l * Hdim,
                                        nullptr, nullptr, acc, SKn, Hdim, 0);
        // local GINE mlp: hmid = relu((h+agg)@W1^T+b1); acc += (hmid@W2^T+b2)*g+b
        gemm128<<<CDIV(SKn, 128), TB>>>(h, agg, wt_l + 1 * HH, lb1 + l * Hdim,
                                        nullptr, nullptr, tmp, SKn, Hdim, FLAG_RELU);
        gemm128<<<CDIV(SKn, 128), TB>>>(tmp, nullptr, wt_l + 2 * HH, lb2 + l * Hdim,
                                        lbn_g + l * Hdim, lbn_b + l * Hdim, acc, SKn, Hdim, FLAG_ACCUM);

        // x_sum = seg_mean(h, safe, N)
        cudaMemsetAsync(xsum, 0, nBytes);
        scatter_add<<<CDIV(SKn * 32, TB), TB>>>(h, node_ids, xsum, SKn);
        scale_rows<<<CDIV(Nn * 32, TB), TB>>>(xsum, cnt, Nn);

        // global GINE
        cudaMemsetAsync(aggN, 0, nBytes);
        edge_msg<<<CDIV(EGn * 32, TB), TB>>>(xsum, edge_index, edge_index + EGn, bid_g, bond_table, aggN, EGn);
        gemm128<<<CDIV(Nn, 128), TB>>>(xsum, aggN, wt_l + 3 * HH, gb1 + l * Hdim,
                                       nullptr, nullptr, tmp, Nn, Hdim, FLAG_RELU);
        gemm128<<<CDIV(Nn, 128), TB>>>(tmp, nullptr, wt_l + 4 * HH, gb2 + l * Hdim,
                                       gbn_g + l * Hdim, gbn_b + l * Hdim, h2, Nn, Hdim, 0);

        // vv path: x_vv_c = seg_mean(h[root], root_safe, N); yvv = x_vv_c @ vvW^T + vvb
        cudaMemsetAsync(xvvc, 0, nBytes);
        root_scatter<<<CDIV(Sn * 32, TB), TB>>>(h, node_ids, xvvc, Sn);
        scale_rows<<<CDIV(Nn * 32, TB), TB>>>(xvvc, rcnt, Nn);
        gemm128<<<CDIV(Nn, 128), TB>>>(xvvc, nullptr, wt_l + 5 * HH, vvb + l * Hdim,
                                       nullptr, nullptr, aggN, Nn, Hdim, 0);  // yvv in aggN

        // kk path: ykk[s] = h[s*K] @ kkW^T + kkb  (row stride K*H)
        gemm128<<<CDIV(Sn, 128), TB>>>(h, nullptr, wt_l + 6 * HH, kkb + l * Hdim,
                                       nullptr, nullptr, ykk, Sn, (long)KSUB * Hdim, 0);

        // h = relu(acc + h2[clamped] + yvv[clamped] + ykk[sub_batch]) * vf
        combine_kernel<<<CDIV(SKn * 32, TB), TB>>>(acc, h2, aggN, ykk, node_ids, sub_batch, h, SKn);
    }

    // node_embs = seg_mean(h, safe, N); out = segment_sum(node_embs, batch, G)
    cudaMemsetAsync(xsum, 0, nBytes);
    scatter_add<<<CDIV(SKn * 32, TB), TB>>>(h, node_ids, xsum, SKn);
    cudaMemsetAsync(d_out, 0, (size_t)out_size * sizeof(float));
    pool_kernel<<<CDIV(Nn * 32, TB), TB>>>(xsum, cnt, batch, (float*)d_out, Nn);
}

// round 3
// speedup vs baseline: 1.2285x; 1.2285x over previous
#include <cuda_runtime.h>
#include <cuda_bf16.h>
#include <cstdint>

#define Hdim 128
#define KSUB 16
#define SK_C 128000
#define N_C  60000
#define S_C  8000
#define L_C  3
#define HH   (Hdim * Hdim)

#define FLAG_RELU  1
#define FLAG_ACCUM 2

#define CDIV(a, b) (((a) + (b) - 1) / (b))

// ------------------------- scratch (static device globals) -------------------------
__device__ float g_h[SK_C * Hdim];
__device__ float g_acc[SK_C * Hdim];
__device__ float g_agg[SK_C * Hdim];
__device__ float g_tmp[SK_C * Hdim];
__device__ float g_xsum[N_C * Hdim];
__device__ float g_aggN[N_C * Hdim];   // reused as yvv output
__device__ float g_h2[N_C * Hdim];
__device__ float g_xvvc[N_C * Hdim];
__device__ float g_ykk[S_C * Hdim];
__device__ int   g_cnt[N_C];
__device__ int   g_rcnt[N_C];
// pre-swizzled bf16 hi/lo weight images, 64KB per matrix (hi 32KB || lo 32KB)
__device__ unsigned char g_wbf[L_C * 7 * 65536];

// ------------------------- helpers -------------------------
__device__ __forceinline__ uint32_t smem_u32(const void* p) {
    uint32_t a;
    asm("{ .reg .u64 t; cvta.to.shared.u64 t, %1; cvt.u32.u64 %0, t; }" : "=r"(a) : "l"(p));
    return a;
}

__device__ __forceinline__ void ldsm4(uint32_t* r, uint32_t addr) {
    asm volatile("ldmatrix.sync.aligned.m8n8.x4.shared.b16 {%0,%1,%2,%3}, [%4];"
        : "=r"(r[0]), "=r"(r[1]), "=r"(r[2]), "=r"(r[3]) : "r"(addr));
}

__device__ __forceinline__ void mma16816(float* c, const uint32_t* a, uint32_t b0, uint32_t b1) {
    asm volatile("mma.sync.aligned.m16n8k16.row.col.f32.bf16.bf16.f32 "
        "{%0,%1,%2,%3}, {%4,%5,%6,%7}, {%8,%9}, {%0,%1,%2,%3};"
        : "+f"(c[0]), "+f"(c[1]), "+f"(c[2]), "+f"(c[3])
        : "r"(a[0]), "r"(a[1]), "r"(a[2]), "r"(a[3]), "r"(b0), "r"(b1));
}

__device__ __forceinline__ uint32_t pack_bf16(float x, float y) {
    __nv_bfloat162 h = __float22bfloat162_rn(make_float2(x, y));
    return *(uint32_t*)&h;
}

// ------------------------- weight prep: bf16 hi/lo split into ldmatrix swizzled image -------------------------
// image[m]: W[n=o][k] rows of 256B, chunk-of-16B XOR swizzled:  off = o*256 + ((k>>3)^(o&7))*16 + (k&7)*2
__global__ void prep_weights(const float* __restrict__ s0, const float* __restrict__ s1,
                             const float* __restrict__ s2, const float* __restrict__ s3,
                             const float* __restrict__ s4, const float* __restrict__ s5,
                             const float* __restrict__ s6, unsigned char* __restrict__ dst, int L)
{
    int i = blockIdx.x * blockDim.x + threadIdx.x;
    int total = L * 7 * HH;
    if (i >= total) return;
    int m = i >> 14;
    int r = i & (HH - 1);
    int o = r >> 7, k = r & 127;
    int l = m / 7, j = m % 7;
    const float* base;
    switch (j) {
        case 0: base = s0; break;
        case 1: base = s1; break;
        case 2: base = s2; break;
        case 3: base = s3; break;
        case 4: base = s4; break;
        case 5: base = s5; break;
        default: base = s6; break;
    }
    float v = base[(size_t)l * HH + o * Hdim + k];
    __nv_bfloat16 hb = __float2bfloat16_rn(v);
    float lo = v - __bfloat162float(hb);
    __nv_bfloat16 lb = __float2bfloat16_rn(lo);
    uint32_t off = (uint32_t)(o * 256 + (((k >> 3) ^ (o & 7)) * 16) + (k & 7) * 2);
    unsigned char* mb = dst + (size_t)m * 65536;
    *(unsigned short*)(mb + off)          = __bfloat16_as_ushort(hb);
    *(unsigned short*)(mb + 32768 + off)  = __bfloat16_as_ushort(lb);
}

// ------------------------- tensor-core GEMM: Y[M,128] = ep((X1 [+X2]) @ W^T + bias) -------------------------
// 512 threads, 256 output rows per CTA.  bf16x3 split (hh + hl + lh) for ~fp32 precision.
// smem: Ah[256*256B]=64K @0, Al 64K @65536, Bh 32K @131072, Bl 32K @163840  -> 192KB
#define SMEM_DYN 196608

__global__ __launch_bounds__(512)
void gemm_mma(const float* __restrict__ X1, const float* __restrict__ X2,
              const unsigned char* __restrict__ WB, const float* __restrict__ bias,
              const float* __restrict__ gamma, const float* __restrict__ beta,
              float* __restrict__ Y, int M, long inStride, int flags)
{
    extern __shared__ char sm[];
    const uint32_t sbase = smem_u32(sm);
    const int tid = threadIdx.x;
    const long m0 = (long)blockIdx.x * 256;

    // copy pre-swizzled W hi/lo (64KB)
    {
        const float4* wsrc = (const float4*)WB;
        float4* wdst = (float4*)(sm + 131072);
#pragma unroll
        for (int i = 0; i < 8; i++)
            wdst[tid + i * 512] = wsrc[tid + i * 512];
    }

    // convert X rows -> bf16 hi/lo swizzled.  task g: row=g>>4, chunk=g&15 (8 cols each)
#pragma unroll
    for (int i = 0; i < 8; i++) {
        int g = tid + i * 512;
        int row = g >> 4, chunk = g & 15;
        long m = m0 + row;
        float v[8];
#pragma unroll
        for (int q = 0; q < 8; q++) v[q] = 0.f;
        if (m < M) {
            const float* xp = X1 + m * inStride + chunk * 8;
            float4 a = *(const float4*)xp;
            float4 b = *(const float4*)(xp + 4);
            v[0] = a.x; v[1] = a.y; v[2] = a.z; v[3] = a.w;
            v[4] = b.x; v[5] = b.y; v[6] = b.z; v[7] = b.w;
            if (X2) {
                const float* yp2 = X2 + m * (long)Hdim + chunk * 8;
                float4 c = *(const float4*)yp2;
                float4 d = *(const float4*)(yp2 + 4);
                v[0] += c.x; v[1] += c.y; v[2] += c.z; v[3] += c.w;
                v[4] += d.x; v[5] += d.y; v[6] += d.z; v[7] += d.w;
            }
        }
        uint4 hi, lo;
        {
            uint32_t hp[4], lp[4];
#pragma unroll
            for (int q = 0; q < 4; q++) {
                float x = v[q * 2], y = v[q * 2 + 1];
                uint32_t h = pack_bf16(x, y);
                __nv_bfloat162 hv = *(__nv_bfloat162*)&h;
                float lx = x - __bfloat162float(hv.x);
                float ly = y - __bfloat162float(hv.y);
                hp[q] = h;
                lp[q] = pack_bf16(lx, ly);
            }
            hi = make_uint4(hp[0], hp[1], hp[2], hp[3]);
            lo = make_uint4(lp[0], lp[1], lp[2], lp[3]);
        }
        uint32_t off = (uint32_t)(row * 256 + ((chunk ^ (row & 7)) * 16));
        *(uint4*)(sm + off)          = hi;
        *(uint4*)(sm + 65536 + off)  = lo;
    }
    __syncthreads();

    // ---- MMA mainloop ----
    const int wid = tid >> 5, lane = tid & 31;
    const int rw = (wid & 7) * 32;    // warp row base within 256
    const int cw = (wid >> 3) * 64;   // warp col base within 128
    const int lg = lane >> 3, lr = lane & 7;

    float c[2][8][4];
#pragma unroll
    for (int mt = 0; mt < 2; mt++)
#pragma unroll
        for (int nt = 0; nt < 8; nt++)
#pragma unroll
            for (int q = 0; q < 4; q++) c[mt][nt][q] = 0.f;

    const int aRow0 = rw + (lg & 1) * 8 + lr;   // + mt*16
    const int bN0   = cw + (lg >> 1) * 8 + lr;  // + ng*16

#pragma unroll 1
    for (int ks = 0; ks < 8; ks++) {
        const int kcA = ks * 2 + (lg >> 1);
        const int kcB = ks * 2 + (lg & 1);
        uint32_t ah[2][4], al[2][4];
#pragma unroll
        for (int mt = 0; mt < 2; mt++) {
            int row = aRow0 + mt * 16;
            uint32_t addr = sbase + row * 256 + ((kcA ^ (row & 7)) * 16);
            ldsm4(ah[mt], addr);
            ldsm4(al[mt], addr + 65536);
        }
#pragma unroll
        for (int ng = 0; ng < 4; ng++) {
            int n = bN0 + ng * 16;
            uint32_t baddr = sbase + 131072 + n * 256 + ((kcB ^ (n & 7)) * 16);
            uint32_t bh[4], bl[4];
            ldsm4(bh, baddr);
            ldsm4(bl, baddr + 32768);
#pragma unroll
            for (int mt = 0; mt < 2; mt++) {
#pragma unroll
                for (int half = 0; half < 2; half++) {
                    int nt = ng * 2 + half;
                    mma16816(c[mt][nt], ah[mt], bh[half * 2], bh[half * 2 + 1]);
                    mma16816(c[mt][nt], ah[mt], bl[half * 2], bl[half * 2 + 1]);
                    mma16816(c[mt][nt], al[mt], bh[half * 2], bh[half * 2 + 1]);
                }
            }
        }
    }

    // ---- epilogue ----
    // D frag: c[0],c[1] -> row base + lane/4, cols (lane%4)*2,+1 ; c[2],c[3] -> row +8
    {
        const int ncol0 = cw + (lane & 3) * 2;
        float2 bi[8], ga[8], be[8];
#pragma unroll
        for (int nt = 0; nt < 8; nt++) {
            bi[nt] = *(const float2*)(bias + ncol0 + nt * 8);
            if (gamma) {
                ga[nt] = *(const float2*)(gamma + ncol0 + nt * 8);
                be[nt] = *(const float2*)(beta  + ncol0 + nt * 8);
            }
        }
#pragma unroll
        for (int mt = 0; mt < 2; mt++) {
#pragma unroll
            for (int h = 0; h < 2; h++) {
                long m = m0 + rw + mt * 16 + h * 8 + (lane >> 2);
                if (m < M) {
                    float* yrow = Y + m * (long)Hdim;
#pragma unroll
                    for (int nt = 0; nt < 8; nt++) {
                        float x = c[mt][nt][h * 2 + 0] + bi[nt].x;
                        float y = c[mt][nt][h * 2 + 1] + bi[nt].y;
                        if (gamma) {
                            x = x * ga[nt].x + be[nt].x;
                            y = y * ga[nt].y + be[nt].y;
                        }
                        if (flags & FLAG_RELU) { x = fmaxf(x, 0.f); y = fmaxf(y, 0.f); }
                        float2* yp = (float2*)(yrow + ncol0 + nt * 8);
                        if (flags & FLAG_ACCUM) {
                            float2 old = *yp;
                            x += old.x; y += old.y;
                        }
                        *yp = make_float2(x, y);
                    }
                }
            }
        }
    }
}

// ------------------------- edge message passing: agg[dst] += relu(x[src] + bond[bid]) -------------------------
__global__ void edge_msg(const float* __restrict__ xin, const int* __restrict__ src,
                         const int* __restrict__ dst, const int* __restrict__ bid,
                         const float* __restrict__ bond, float* __restrict__ agg, int E)
{
    int w = (blockIdx.x * blockDim.x + threadIdx.x) >> 5;
    int l = threadIdx.x & 31;
    if (w >= E) return;
    int s = __ldg(src + w), d = __ldg(dst + w), b = __ldg(bid + w);
    float4 hv = *(const float4*)(xin + (size_t)s * Hdim + l * 4);
    float4 bv = *(const float4*)(bond + (size_t)b * Hdim + l * 4);
    float m0 = fmaxf(hv.x + bv.x, 0.f);
    float m1 = fmaxf(hv.y + bv.y, 0.f);
    float m2 = fmaxf(hv.z + bv.z, 0.f);
    float m3 = fmaxf(hv.w + bv.w, 0.f);
    float* o = agg + (size_t)d * Hdim + l * 4;
    atomicAdd(o + 0, m0);
    atomicAdd(o + 1, m1);
    atomicAdd(o + 2, m2);
    atomicAdd(o + 3, m3);
}

// ------------------------- counts -------------------------
__global__ void count_kernel(const int* __restrict__ node_ids, int* __restrict__ cnt, int SKn)
{
    int i = blockIdx.x * blockDim.x + threadIdx.x;
    if (i >= SKn) return;
    int nid = node_ids[i];
    if (nid >= 0) atomicAdd(&cnt[nid], 1);
}
__global__ void rcount_kernel(const int* __restrict__ node_ids, int* __restrict__ rcnt, int Sn)
{
    int s = blockIdx.x * blockDim.x + threadIdx.x;
    if (s >= Sn) return;
    int nid = node_ids[s * KSUB];
    if (nid >= 0) atomicAdd(&rcnt[nid], 1);
}

// ------------------------- init h -------------------------
__global__ void init_h(const float* __restrict__ atom_table, const float* __restrict__ role_table,
                       const int* __restrict__ atom_ids, const int* __restrict__ node_ids,
                       float* __restrict__ h, int SKn)
{
    int t = blockIdx.x * blockDim.x + threadIdx.x;
    int row = t >> 5;
    if (row >= SKn) return;
    int q = t & 31;
    float4 out = make_float4(0.f, 0.f, 0.f, 0.f);
    if (node_ids[row] >= 0) {
        int aid = atom_ids[row];
        float4 v = *(const float4*)(atom_table + (size_t)aid * Hdim + q * 4);
        const float* role = role_table + (((row & (KSUB - 1)) == 0) ? Hdim : 0);
        float4 r = *(const float4*)(role + q * 4);
        out = make_float4(v.x + r.x, v.y + r.y, v.z + r.z, v.w + r.w);
    }
    *(float4*)(h + (size_t)row * Hdim + q * 4) = out;
}

// ------------------------- scatter add: dst[nid] += src[row] -------------------------
__global__ void scatter_add(const float* __restrict__ src, const int* __restrict__ node_ids,
                            float* __restrict__ dst, int SKn)
{
    int t = blockIdx.x * blockDim.x + threadIdx.x;
    int row = t >> 5;
    if (row >= SKn) return;
    int nid = node_ids[row];
    if (nid < 0) return;
    int q = t & 31;
    float4 v = *(const float4*)(src + (size_t)row * Hdim + q * 4);
    float* o = dst + (size_t)nid * Hdim + q * 4;
    atomicAdd(o + 0, v.x);
    atomicAdd(o + 1, v.y);
    atomicAdd(o + 2, v.z);
    atomicAdd(o + 3, v.w);
}

__global__ void root_scatter(const float* __restrict__ h, const int* __restrict__ node_ids,
                             float* __restrict__ dst, int Sn)
{
    int t = blockIdx.x * blockDim.x + threadIdx.x;
    int s = t >> 5;
    if (s >= Sn) return;
    int row = s * KSUB;
    int nid = node_ids[row];
    if (nid < 0) return;
    int q = t & 31;
    float4 v = *(const float4*)(h + (size_t)row * Hdim + q * 4);
    float* o = dst + (size_t)nid * Hdim + q * 4;
    atomicAdd(o + 0, v.x);
    atomicAdd(o + 1, v.y);
    atomicAdd(o + 2, v.z);
    atomicAdd(o + 3, v.w);
}

// ------------------------- scale rows by 1/max(cnt,1) -------------------------
__global__ void scale_rows(float* __restrict__ x, const int* __restrict__ cnt, int Nn)
{
    int t = blockIdx.x * blockDim.x + threadIdx.x;
    int n = t >> 5;
    if (n >= Nn) return;
    int q = t & 31;
    float inv = 1.f / (float)max(cnt[n], 1);
    float4* p = (float4*)(x + (size_t)n * Hdim + q * 4);
    float4 v = *p;
    v.x *= inv; v.y *= inv; v.z *= inv; v.w *= inv;
    *p = v;
}

// ------------------------- per-layer combine -------------------------
__global__ void combine_kernel(const float* __restrict__ acc, const float* __restrict__ h2,
                               const float* __restrict__ yvv, const float* __restrict__ ykk,
                               const int* __restrict__ node_ids, const int* __restrict__ sub_batch,
                               float* __restrict__ h, int SKn)
{
    int t = blockIdx.x * blockDim.x + threadIdx.x;
    int row = t >> 5;
    if (row >= SKn) return;
    int q = t & 31;
    int nid = node_ids[row];
    float4 out = make_float4(0.f, 0.f, 0.f, 0.f);
    if (nid >= 0) {
        int sb = sub_batch[row];
        float4 a = *(const float4*)(acc + (size_t)row * Hdim + q * 4);
        float4 b = *(const float4*)(h2  + (size_t)nid * Hdim + q * 4);
        float4 c = *(const float4*)(yvv + (size_t)nid * Hdim + q * 4);
        float4 d = *(const float4*)(ykk + (size_t)sb  * Hdim + q * 4);
        out.x = fmaxf(a.x + b.x + c.x + d.x, 0.f);
        out.y = fmaxf(a.y + b.y + c.y + d.y, 0.f);
        out.z = fmaxf(a.z + b.z + c.z + d.z, 0.f);
        out.w = fmaxf(a.w + b.w + c.w + d.w, 0.f);
    }
    *(float4*)(h + (size_t)row * Hdim + q * 4) = out;
}

// ------------------------- final pool -------------------------
__global__ void pool_kernel(const float* __restrict__ xsum, const int* __restrict__ cnt,
                            const int* __restrict__ batch, float* __restrict__ out, int Nn)
{
    int t = blockIdx.x * blockDim.x + threadIdx.x;
    int n = t >> 5;
    if (n >= Nn) return;
    int q = t & 31;
    float inv = 1.f / (float)max(cnt[n], 1);
    int g = batch[n];
    float4 v = *(const float4*)(xsum + (size_t)n * Hdim + q * 4);
    float* o = out + (size_t)g * Hdim + q * 4;
    atomicAdd(o + 0, v.x * inv);
    atomicAdd(o + 1, v.y * inv);
    atomicAdd(o + 2, v.z * inv);
    atomicAdd(o + 3, v.w * inv);
}

// ------------------------- host orchestration -------------------------
extern "C" void kernel_launch(void* const* d_in, const int* in_sizes, int n_in,
                              void* d_out, int out_size)
{
    const float* atom_table = (const float*)d_in[0];
    const float* bond_table = (const float*)d_in[1];
    const float* role_table = (const float*)d_in[2];
    const float* lW1  = (const float*)d_in[3];
    const float* lb1  = (const float*)d_in[4];
    const float* lW2  = (const float*)d_in[5];
    const float* lb2  = (const float*)d_in[6];
    const float* gW1  = (const float*)d_in[7];
    const float* gb1  = (const float*)d_in[8];
    const float* gW2  = (const float*)d_in[9];
    const float* gb2  = (const float*)d_in[10];
    const float* lbn_g = (const float*)d_in[11];
    const float* lbn_b = (const float*)d_in[12];
    const float* gbn_g = (const float*)d_in[13];
    const float* gbn_b = (const float*)d_in[14];
    const float* skipW = (const float*)d_in[15];
    const float* skipb = (const float*)d_in[16];
    const float* vvW  = (const float*)d_in[17];
    const float* vvb  = (const float*)d_in[18];
    const float* kkW  = (const float*)d_in[19];
    const float* kkb  = (const float*)d_in[20];
    const int* atom_ids  = (const int*)d_in[21];
    const int* bid_i     = (const int*)d_in[22];
    const int* bid_g     = (const int*)d_in[23];
    const int* intra_ei  = (const int*)d_in[24];
    const int* node_ids  = (const int*)d_in[25];
    const int* edge_index = (const int*)d_in[26];
    const int* sub_batch = (const int*)d_in[27];
    const int* batch     = (const int*)d_in[28];

    const int SKn = in_sizes[21];
    const int EIn = in_sizes[22];
    const int EGn = in_sizes[23];
    const int Nn  = in_sizes[28];
    const int Sn  = SKn / KSUB;
    const int L   = in_sizes[4] / Hdim;

    float *h, *acc, *agg, *tmp, *xsum, *aggN, *h2, *xvvc, *ykk;
    int *cnt, *rcnt;
    unsigned char* wbf;
    cudaGetSymbolAddress((void**)&h,    g_h);
    cudaGetSymbolAddress((void**)&acc,  g_acc);
    cudaGetSymbolAddress((void**)&agg,  g_agg);
    cudaGetSymbolAddress((void**)&tmp,  g_tmp);
    cudaGetSymbolAddress((void**)&xsum, g_xsum);
    cudaGetSymbolAddress((void**)&aggN, g_aggN);
    cudaGetSymbolAddress((void**)&h2,   g_h2);
    cudaGetSymbolAddress((void**)&xvvc, g_xvvc);
    cudaGetSymbolAddress((void**)&ykk,  g_ykk);
    cudaGetSymbolAddress((void**)&cnt,  g_cnt);
    cudaGetSymbolAddress((void**)&rcnt, g_rcnt);
    cudaGetSymbolAddress((void**)&wbf,  g_wbf);

    cudaFuncSetAttribute(gemm_mma, cudaFuncAttributeMaxDynamicSharedMemorySize, SMEM_DYN);

    const int TB = 256;
    const size_t skBytes = (size_t)SKn * Hdim * sizeof(float);
    const size_t nBytes  = (size_t)Nn  * Hdim * sizeof(float);

#define GEMM(X1p, X2p, widx, biasp, gammap, betap, Yp, Mv, strv, flg) \
    gemm_mma<<<CDIV((Mv), 256), 512, SMEM_DYN>>>((X1p), (X2p), wbf + (size_t)(widx) * 65536, \
        (biasp), (gammap), (betap), (Yp), (Mv), (strv), (flg))

    // per-call prep: weight split + counts + init
    prep_weights<<<CDIV(L * 7 * HH, TB), TB>>>(skipW, lW1, lW2, gW1, gW2, vvW, kkW, wbf, L);
    cudaMemsetAsync(cnt,  0, (size_t)Nn * sizeof(int));
    cudaMemsetAsync(rcnt, 0, (size_t)Nn * sizeof(int));
    count_kernel<<<CDIV(SKn, TB), TB>>>(node_ids, cnt, SKn);
    rcount_kernel<<<CDIV(Sn, TB), TB>>>(node_ids, rcnt, Sn);
    init_h<<<CDIV(SKn * 32, TB), TB>>>(atom_table, role_table, atom_ids, node_ids, h, SKn);

    for (int l = 0; l < L; l++) {
        const int w0 = l * 7;

        // local GINE aggregation
        cudaMemsetAsync(agg, 0, skBytes);
        edge_msg<<<CDIV(EIn * 32, TB), TB>>>(h, intra_ei, intra_ei + EIn, bid_i, bond_table, agg, EIn);

        // skip path -> acc
        GEMM(h, nullptr, w0 + 0, skipb + l * Hdim, nullptr, nullptr, acc, SKn, (long)Hdim, 0);
        // local GINE mlp
        GEMM(h, agg, w0 + 1, lb1 + l * Hdim, nullptr, nullptr, tmp, SKn, (long)Hdim, FLAG_RELU);
        GEMM(tmp, nullptr, w0 + 2, lb2 + l * Hdim, lbn_g + l * Hdim, lbn_b + l * Hdim, acc, SKn, (long)Hdim, FLAG_ACCUM);

        // x_sum = seg_mean(h, safe, N)
        cudaMemsetAsync(xsum, 0, nBytes);
        scatter_add<<<CDIV(SKn * 32, TB), TB>>>(h, node_ids, xsum, SKn);
        scale_rows<<<CDIV(Nn * 32, TB), TB>>>(xsum, cnt, Nn);

        // global GINE
        cudaMemsetAsync(aggN, 0, nBytes);
        edge_msg<<<CDIV(EGn * 32, TB), TB>>>(xsum, edge_index, edge_index + EGn, bid_g, bond_table, aggN, EGn);
        GEMM(xsum, aggN, w0 + 3, gb1 + l * Hdim, nullptr, nullptr, tmp, Nn, (long)Hdim, FLAG_RELU);
        GEMM(tmp, nullptr, w0 + 4, gb2 + l * Hdim, gbn_g + l * Hdim, gbn_b + l * Hdim, h2, Nn, (long)Hdim, 0);

        // vv path
        cudaMemsetAsync(xvvc, 0, nBytes);
        root_scatter<<<CDIV(Sn * 32, TB), TB>>>(h, node_ids, xvvc, Sn);
        scale_rows<<<CDIV(Nn * 32, TB), TB>>>(xvvc, rcnt, Nn);
        GEMM(xvvc, nullptr, w0 + 5, vvb + l * Hdim, nullptr, nullptr, aggN, Nn, (long)Hdim, 0);  // yvv in aggN

        // kk path (strided rows: roots only)
        GEMM(h, nullptr, w0 + 6, kkb + l * Hdim, nullptr, nullptr, ykk, Sn, (long)KSUB * Hdim, 0);

        // h = relu(acc + h2[clamped] + yvv[clamped] + ykk[sub_batch]) * vf
        combine_kernel<<<CDIV(SKn * 32, TB), TB>>>(acc, h2, aggN, ykk, node_ids, sub_batch, h, SKn);
    }

    // node_embs = seg_mean(h, safe, N); out = segment_sum(node_embs, batch, G)
    cudaMemsetAsync(xsum, 0, nBytes);
    scatter_add<<<CDIV(SKn * 32, TB), TB>>>(h, node_ids, xsum, SKn);
    cudaMemsetAsync(d_out, 0, (size_t)out_size * sizeof(float));
    pool_kernel<<<CDIV(Nn * 32, TB), TB>>>(xsum, cnt, batch, (float*)d_out, Nn);
#undef GEMM
}